// round 6
// baseline (speedup 1.0000x reference)
#include <cuda_runtime.h>
#include <cstdint>

#define GRID_N   64
#define GRID_N3  (64 * 64 * 64)      // 262144
#define BMAX     8
#define NCELLS   (BMAX * GRID_N3)    // 2097152
#define EPS_CLIP 1e-5f
#define EPS_DIV  1e-7f

// Scratch: interleaved {weight, weight*prob} per cell, with 2-cell guard pads
// front and back so the uniform 4-cell RED windows may spill zero-valued adds
// without going out of bounds. 16 MB payload -> L2 resident.
#define PAD 2
__device__ __align__(16) float2 g_grid_raw[PAD + NCELLS + PAD];

__device__ __forceinline__ void red_add_v4(float2* addr, float a, float b, float c, float d) {
    asm volatile("red.global.add.v4.f32 [%0], {%1, %2, %3, %4};"
                 :: "l"(addr), "f"(a), "f"(b), "f"(c), "f"(d) : "memory");
}

// ---------------------------------------------------------------------------
// Pass 1: zero scratch (grid-stride, 8 x float4 = 128B per thread per step)
// ---------------------------------------------------------------------------
__global__ void __launch_bounds__(256) zero_kernel(int n4) {
    float4* g = reinterpret_cast<float4*>(g_grid_raw);
    int stride = gridDim.x * blockDim.x;
    const float4 z = make_float4(0.f, 0.f, 0.f, 0.f);
    for (int i = blockIdx.x * blockDim.x + threadIdx.x; i < n4; i += stride)
        g[i] = z;
}

// ---------------------------------------------------------------------------
// Pass 2: P2G scatter. One thread per particle.
// Fully branchless 27-tap stencil: per (x,y) column exactly two red.v4
// instructions covering the aligned 4-cell z-window; boundary taps carry
// weight 0.0 into guard/neighbor cells (numerical no-op).
// ---------------------------------------------------------------------------
__global__ void __launch_bounds__(256) scatter_kernel(
    const float* __restrict__ pos,
    const float* __restrict__ prob,
    const int*   __restrict__ bidx,
    int L)
{
    int i = blockIdx.x * blockDim.x + threadIdx.x;
    if (i >= L) return;

    const float lo = EPS_CLIP, hi = 1.0f - EPS_CLIP;
    float px = fminf(fmaxf(__ldg(&pos[3 * i + 0]), lo), hi);
    float py = fminf(fmaxf(__ldg(&pos[3 * i + 1]), lo), hi);
    float pz = fminf(fmaxf(__ldg(&pos[3 * i + 2]), lo), hi);

    // Xp = pos / DX == pos * 64 exactly (DX = 1/64)
    float xp = px * 64.0f, yp = py * 64.0f, zp = pz * 64.0f;
    int bx = (int)xp, by = (int)yp, bz = (int)zp;   // floor (coords >= 0)
    float fx = xp - (float)bx;
    float fy = yp - (float)by;
    float fz = zp - (float)bz;

    // quadratic B-spline weights
    float wx0 = 0.5f * (1.0f - fx) * (1.0f - fx);
    float wx1 = 0.75f - (fx - 0.5f) * (fx - 0.5f);
    float wx2 = 0.5f * fx * fx;
    float wy0 = 0.5f * (1.0f - fy) * (1.0f - fy);
    float wy1 = 0.75f - (fy - 0.5f) * (fy - 0.5f);
    float wy2 = 0.5f * fy * fy;
    float wz0 = 0.5f * (1.0f - fz) * (1.0f - fz);
    float wz1 = 0.75f - (fz - 0.5f) * (fz - 0.5f);
    float wz2 = 0.5f * fz * fz;

    // zero out-of-box taps (adds of 0.0 land in guard/neighbor cells harmlessly)
    if (bz < 1)  wz0 = 0.0f;
    if (bz > 62) wz2 = 0.0f;
    float wxa0 = (bx >= 1)  ? wx0 : 0.0f;
    float wxa2 = (bx <= 62) ? wx2 : 0.0f;
    float wya0 = (by >= 1)  ? wy0 : 0.0f;
    float wya2 = (by <= 62) ? wy2 : 0.0f;

    // parity-aligned 4-cell z-window: cells z0..z0+3, z0 = (bz-1) & ~1
    // bz even -> (0, wz0, wz1, wz2) ; bz odd -> (wz0, wz1, wz2, 0)
    int  z0   = (bz - 1) & ~1;                       // may be -2 (guard pad)
    bool oddz = (bz & 1) != 0;
    float c0 = oddz ? wz0 : 0.0f;
    float c1 = oddz ? wz1 : wz0;
    float c2 = oddz ? wz2 : wz1;
    float c3 = oddz ? 0.0f : wz2;

    float pr = __ldg(&prob[i]);
    float d0 = c0 * pr, d1 = c1 * pr, d2 = c2 * pr, d3 = c3 * pr;

    // clamped x/y tap coordinates (weights already zeroed when clamped)
    int tx0 = max(bx - 1, 0) << 12;          // *4096
    int tx1 = bx << 12;
    int tx2 = min(bx + 1, 63) << 12;
    int ty0 = max(by - 1, 0) << 6;           // *64
    int ty1 = by << 6;
    int ty2 = min(by + 1, 63) << 6;

    float2* gbase = g_grid_raw + PAD + (unsigned)__ldg(&bidx[i]) * GRID_N3 + z0;

    int   xo[3] = {tx0, tx1, tx2};
    float wxv[3] = {wxa0, wx1, wxa2};
    int   yo[3] = {ty0, ty1, ty2};
    float wyv[3] = {wya0, wy1, wya2};

    #pragma unroll
    for (int ox = 0; ox < 3; ox++) {
        #pragma unroll
        for (int oy = 0; oy < 3; oy++) {
            float wxy = wxv[ox] * wyv[oy];
            float2* p = gbase + (xo[ox] + yo[oy]);
            red_add_v4(p,     wxy * c0, wxy * d0, wxy * c1, wxy * d1);
            red_add_v4(p + 2, wxy * c2, wxy * d2, wxy * c3, wxy * d3);
        }
    }
}

// ---------------------------------------------------------------------------
// Pass 3: out = wp / (w + eps). 4 cells per thread.
// ---------------------------------------------------------------------------
__global__ void __launch_bounds__(256) divide_kernel(float* __restrict__ out, int n4) {
    int i = blockIdx.x * blockDim.x + threadIdx.x;
    if (i >= n4) return;
    const float4* g = reinterpret_cast<const float4*>(g_grid_raw + PAD);
    float4 a = g[2 * i];                  // cells 4i,   4i+1
    float4 b = g[2 * i + 1];              // cells 4i+2, 4i+3
    float4 r;
    r.x = a.y / (a.x + EPS_DIV);
    r.y = a.w / (a.z + EPS_DIV);
    r.z = b.y / (b.x + EPS_DIV);
    r.w = b.w / (b.z + EPS_DIV);
    reinterpret_cast<float4*>(out)[i] = r;
}

// ---------------------------------------------------------------------------
extern "C" void kernel_launch(void* const* d_in, const int* in_sizes, int n_in,
                              void* d_out, int out_size)
{
    const float* pos  = (const float*)d_in[0];
    const float* prob = (const float*)d_in[1];
    const int*   bidx = (const int*)d_in[2];
    int L = in_sizes[1];               // particle count (prob element count)

    // zero entire raw array (incl. guard pads)
    int n4_zero = (int)(sizeof(g_grid_raw) / sizeof(float4));
    zero_kernel<<<592, 256>>>(n4_zero);          // grid-stride, ~128B/thread/iter

    scatter_kernel<<<(L + 255) / 256, 256>>>(pos, prob, bidx, L);

    int n4_div = out_size / 4;                   // 4 output cells per thread
    divide_kernel<<<(n4_div + 255) / 256, 256>>>((float*)d_out, n4_div);
}